// round 7
// baseline (speedup 1.0000x reference)
#include <cuda_runtime.h>
#include <cuda_bf16.h>
#include <math.h>

#define BS   16384
#define NQ   16
#define HID  512

// ---------------- scratch (static __device__ — allocation-free) ----------------
__device__ float g_s1[BS * HID];
__device__ float g_h1[BS * HID];   // h1; reused as u1 = s1*g1 after K3
__device__ float g_d2[BS * HID];
__device__ float g_u2[BS * HID];
__device__ float g_g1[BS * HID];   // d1 = s1*(1-s1)*g1 after K3
__device__ float g_p [BS * HID];   // p_k = sum_{j<16} W1[j,k]*qd_j
__device__ float g_w [BS * HID];   // w_m = d2_m * v_m,  v = (s1*p) @ W2
__device__ float g_Q [(size_t)BS * 16 * HID];   // Q_lo rows, [ (b*16+i)*512 + m ]
__device__ float g_A [BS * NQ * NQ];
__device__ float g_rhs[BS * NQ];

// ---------------- f32x2 helpers ----------------
__device__ __forceinline__ void fma2(unsigned long long& d, unsigned long long a, unsigned long long b) {
    asm("fma.rn.f32x2 %0, %1, %2, %0;" : "+l"(d) : "l"(a), "l"(b));
}
__device__ __forceinline__ unsigned long long pack2(float v) {
    unsigned long long r;
    asm("mov.b64 %0, {%1, %1};" : "=l"(r) : "f"(v));
    return r;
}
__device__ __forceinline__ float2 unpack2(unsigned long long v) {
    float2 r;
    asm("mov.b64 {%0, %1}, %2;" : "=f"(r.x), "=f"(r.y) : "l"(v));
    return r;
}

// ---------------- K1: z1 = x@W1 + b1 -> s1, h1 ; p = W1_top^T qd ----------------
#define K1_SMEM ((32*512 + 256) * 4)
__global__ __launch_bounds__(256) void k1_layer1(const float* __restrict__ x,
                                                 const float* __restrict__ W1,
                                                 const float* __restrict__ b1) {
    extern __shared__ float sm1[];
    float* W1s = sm1;
    float* xs  = sm1 + 32 * 512;
    int tid = threadIdx.x;
    int b0  = blockIdx.x * 8;

    for (int idx = tid; idx < 32 * 512; idx += 256) W1s[idx] = W1[idx];
    xs[tid] = x[b0 * 32 + tid];
    __syncthreads();

    for (int q = 0; q < 16; ++q) {
        int idx = q * 256 + tid;
        int b = idx >> 9, k = idx & 511;
        float acc = b1[k];
        float accp = 0.f;
        const float* xr = xs + b * 32;
#pragma unroll
        for (int j = 0; j < 32; ++j) {
            float w = W1s[j * 512 + k];
            acc = fmaf(xr[j], w, acc);
            if (j < 16) accp = fmaf(xr[16 + j], w, accp);
        }
        float s = 1.f / (1.f + expf(-acc));
        float h = fmaxf(acc, 0.f) + log1pf(expf(-fabsf(acc)));
        int gi = (b0 + b) * 512 + k;
        g_s1[gi] = s;
        g_h1[gi] = h;
        g_p[gi]  = accp;
    }
}

// ---------------- K2: z2 = h1@W2 + b2 -> d2,u2 ; fused v = (s1*p)@W2 -> w ----------------
__global__ __launch_bounds__(256) void k2_layer2(const float* __restrict__ W2,
                                                 const float* __restrict__ b2,
                                                 const float* __restrict__ W3) {
    __shared__ __align__(16) float As[64][17];
    __shared__ __align__(16) float As2[64][17];
    __shared__ __align__(16) float Bs[16][64];
    int tid = threadIdx.x;
    int b0 = blockIdx.x * 64;
    int m0 = blockIdx.y * 64;
    int ty = tid >> 4, tx = tid & 15;
    float acc[4][4] = {};
    float acc2[4][4] = {};

    for (int k0 = 0; k0 < HID; k0 += 16) {
        __syncthreads();
#pragma unroll
        for (int r = 0; r < 4; ++r) {
            int idx = tid + r * 256;
            int gi = (b0 + (idx >> 4)) * HID + k0 + (idx & 15);
            As[idx >> 4][idx & 15]  = g_h1[gi];
            As2[idx >> 4][idx & 15] = g_s1[gi] * g_p[gi];
        }
#pragma unroll
        for (int r = 0; r < 4; ++r) {
            int idx = tid + r * 256;
            Bs[idx >> 6][idx & 63] = W2[(k0 + (idx >> 6)) * HID + m0 + (idx & 63)];
        }
        __syncthreads();
#pragma unroll
        for (int kk = 0; kk < 16; ++kk) {
            float4 bv = *reinterpret_cast<const float4*>(&Bs[kk][tx * 4]);
#pragma unroll
            for (int i = 0; i < 4; ++i) {
                float a = As[ty * 4 + i][kk];
                acc[i][0] = fmaf(a, bv.x, acc[i][0]);
                acc[i][1] = fmaf(a, bv.y, acc[i][1]);
                acc[i][2] = fmaf(a, bv.z, acc[i][2]);
                acc[i][3] = fmaf(a, bv.w, acc[i][3]);
                float a2 = As2[ty * 4 + i][kk];
                acc2[i][0] = fmaf(a2, bv.x, acc2[i][0]);
                acc2[i][1] = fmaf(a2, bv.y, acc2[i][1]);
                acc2[i][2] = fmaf(a2, bv.z, acc2[i][2]);
                acc2[i][3] = fmaf(a2, bv.w, acc2[i][3]);
            }
        }
    }
#pragma unroll
    for (int i = 0; i < 4; ++i) {
        int b = b0 + ty * 4 + i;
#pragma unroll
        for (int j = 0; j < 4; ++j) {
            int m = m0 + tx * 4 + j;
            float z = acc[i][j] + b2[m];
            float s = 1.f / (1.f + expf(-z));
            float w3v = W3[m];
            float d2v = s * (1.f - s) * w3v;
            g_d2[b * HID + m] = d2v;
            g_u2[b * HID + m] = s * w3v;
            g_w [b * HID + m] = acc2[i][j] * d2v;
        }
    }
}

// ---------------- K3: g1 = u2 @ W2^T -> u1 (g_h1), d1 (g_g1) ----------------
__global__ __launch_bounds__(256) void k3_g1(const float* __restrict__ W2) {
    __shared__ float As[64][17];
    __shared__ float Bs[16][68];
    int tid = threadIdx.x;
    int b0  = blockIdx.x * 64;
    int k00 = blockIdx.y * 64;
    int ty = tid >> 4, tx = tid & 15;
    float acc[4][4] = {};

    for (int m0 = 0; m0 < HID; m0 += 16) {
        __syncthreads();
#pragma unroll
        for (int r = 0; r < 4; ++r) {
            int idx = tid + r * 256;
            As[idx >> 4][idx & 15] = g_u2[(b0 + (idx >> 4)) * HID + m0 + (idx & 15)];
        }
#pragma unroll
        for (int r = 0; r < 4; ++r) {
            int idx = tid + r * 256;
            Bs[idx & 15][idx >> 4] = W2[(k00 + (idx >> 4)) * HID + m0 + (idx & 15)];
        }
        __syncthreads();
#pragma unroll
        for (int mm = 0; mm < 16; ++mm) {
            float v0 = Bs[mm][tx * 4 + 0], v1 = Bs[mm][tx * 4 + 1];
            float v2 = Bs[mm][tx * 4 + 2], v3 = Bs[mm][tx * 4 + 3];
#pragma unroll
            for (int i = 0; i < 4; ++i) {
                float a = As[ty * 4 + i][mm];
                acc[i][0] = fmaf(a, v0, acc[i][0]);
                acc[i][1] = fmaf(a, v1, acc[i][1]);
                acc[i][2] = fmaf(a, v2, acc[i][2]);
                acc[i][3] = fmaf(a, v3, acc[i][3]);
            }
        }
    }
#pragma unroll
    for (int i = 0; i < 4; ++i) {
        int b = b0 + ty * 4 + i;
#pragma unroll
        for (int j = 0; j < 4; ++j) {
            int gi = b * HID + k00 + tx * 4 + j;
            float g = acc[i][j];
            float s = g_s1[gi];
            g_h1[gi] = s * g;                 // u1
            g_g1[gi] = s * (1.f - s) * g;     // d1
        }
    }
}

// ---------------- K_jac: rhs_base = jac_top - W1_lo*(d1*p)  (round-4 exact) ----------------
#define KJ_SMEM (32 * 513 * 4)
__global__ __launch_bounds__(256) void k_jac(const float* __restrict__ W1) {
    extern __shared__ float W1s[];   // [j*513 + k]
    int tid = threadIdx.x;
    int b0  = blockIdx.x * 8;
    for (int idx = tid; idx < 32 * 512; idx += 256)
        W1s[(idx >> 9) * 513 + (idx & 511)] = W1[idx];
    __syncthreads();

    int s = tid >> 5, lane = tid & 31;
    int i = lane & 15, half = lane >> 4;
    int b = b0 + s;
    float accJ = 0.f, accR = 0.f;
    const float* u1p = g_h1 + (size_t)b * 512;
    const float* d1p = g_g1 + (size_t)b * 512;
    const float* pp  = g_p  + (size_t)b * 512;
    for (int t = 0; t < 256; ++t) {
        int k = half * 256 + t;
        accJ = fmaf(W1s[i * 513 + k], u1p[k], accJ);
        accR = fmaf(W1s[(16 + i) * 513 + k], d1p[k] * pp[k], accR);
    }
    accJ += __shfl_xor_sync(0xffffffffu, accJ, 16);
    accR += __shfl_xor_sync(0xffffffffu, accR, 16);
    if (lane < 16) g_rhs[(size_t)b * 16 + i] = accJ - accR;
}

// ---------------- K4a: Q_big GEMM, double-buffered (bit-exact vs round 4) ----------------
// smem floats: W1s 512*17 | s1s 512*9 | As[2] 2*2112 | Bs[2] 2*2112
#define K4A_FLOATS (512*17 + 512*9 + 4*16*132)
#define K4A_SMEM   (K4A_FLOATS * 4)

__global__ __launch_bounds__(256, 2) void k4a_qgemm(const float* __restrict__ W1,
                                                    const float* __restrict__ W2) {
    extern __shared__ float sma[];
    float* W1s = sma;                 // [k*17 + i]
    float* s1s = W1s + 512 * 17;      // [k*9 + s]
    float* Asb = s1s + 512 * 9;       // 2 buffers x 2112
    float* Bsb = Asb + 2 * 2112;      // 2 buffers x 2112

    int tid = threadIdx.x;
    int r0 = blockIdx.x * 128;
    int n0 = blockIdx.y * 128;
    int s0 = blockIdx.x * 8;
    int tx = tid & 15, ty = tid >> 4;

    for (int idx = tid; idx < 16 * 512; idx += 256) {
        int i = idx >> 9, k = idx & 511;
        W1s[k * 17 + i] = W1[(16 + i) * 512 + k];
    }
    for (int idx = tid; idx < 8 * 512; idx += 256) {
        int s = idx >> 9, k = idx & 511;
        s1s[k * 9 + s] = g_s1[(size_t)(s0 + s) * 512 + k];
    }
    __syncthreads();

    // prime buffer 0 (kt = 0)
#pragma unroll
    for (int it = 0; it < 8; ++it) {
        int idx = it * 256 + tid;
        int kk = idx >> 7, row = idx & 127;
        Asb[kk * 132 + row] = W1s[kk * 17 + (row & 15)] * s1s[kk * 9 + (row >> 4)];
    }
#pragma unroll
    for (int it = 0; it < 2; ++it) {
        int idx = it * 256 + tid;
        int kk = idx >> 5, c4 = idx & 31;
        *reinterpret_cast<float4*>(&Bsb[kk * 132 + c4 * 4]) =
            *reinterpret_cast<const float4*>(&W2[(size_t)kk * 512 + n0 + c4 * 4]);
    }
    __syncthreads();

    unsigned long long acc[8][4] = {};

    for (int kt = 0; kt < 32; ++kt) {
        const float* As = Asb + (kt & 1) * 2112;
        const float* Bs = Bsb + (kt & 1) * 2112;
        float* Asn = Asb + ((kt + 1) & 1) * 2112;
        float* Bsn = Bsb + ((kt + 1) & 1) * 2112;

        // prefetch next tile into registers (values identical to round-4 fills)
        float a_pre[8];
        float4 b_pre[2];
        if (kt < 31) {
            int k0n = (kt + 1) * 16;
#pragma unroll
            for (int it = 0; it < 8; ++it) {
                int idx = it * 256 + tid;
                int kk = idx >> 7, row = idx & 127;
                a_pre[it] = W1s[(k0n + kk) * 17 + (row & 15)] *
                            s1s[(k0n + kk) * 9 + (row >> 4)];
            }
#pragma unroll
            for (int it = 0; it < 2; ++it) {
                int idx = it * 256 + tid;
                int kk = idx >> 5, c4 = idx & 31;
                b_pre[it] = *reinterpret_cast<const float4*>(
                    &W2[(size_t)(k0n + kk) * 512 + n0 + c4 * 4]);
            }
        }

#pragma unroll
        for (int kk = 0; kk < 16; ++kk) {
            float4 a0 = *reinterpret_cast<const float4*>(&As[kk * 132 + ty * 8]);
            float4 a1 = *reinterpret_cast<const float4*>(&As[kk * 132 + ty * 8 + 4]);
            ulonglong2 b01 = *reinterpret_cast<const ulonglong2*>(&Bs[kk * 132 + tx * 8]);
            ulonglong2 b23 = *reinterpret_cast<const ulonglong2*>(&Bs[kk * 132 + tx * 8 + 4]);
            unsigned long long ap;
            ap = pack2(a0.x);
            fma2(acc[0][0], b01.x, ap); fma2(acc[0][1], b01.y, ap);
            fma2(acc[0][2], b23.x, ap); fma2(acc[0][3], b23.y, ap);
            ap = pack2(a0.y);
            fma2(acc[1][0], b01.x, ap); fma2(acc[1][1], b01.y, ap);
            fma2(acc[1][2], b23.x, ap); fma2(acc[1][3], b23.y, ap);
            ap = pack2(a0.z);
            fma2(acc[2][0], b01.x, ap); fma2(acc[2][1], b01.y, ap);
            fma2(acc[2][2], b23.x, ap); fma2(acc[2][3], b23.y, ap);
            ap = pack2(a0.w);
            fma2(acc[3][0], b01.x, ap); fma2(acc[3][1], b01.y, ap);
            fma2(acc[3][2], b23.x, ap); fma2(acc[3][3], b23.y, ap);
            ap = pack2(a1.x);
            fma2(acc[4][0], b01.x, ap); fma2(acc[4][1], b01.y, ap);
            fma2(acc[4][2], b23.x, ap); fma2(acc[4][3], b23.y, ap);
            ap = pack2(a1.y);
            fma2(acc[5][0], b01.x, ap); fma2(acc[5][1], b01.y, ap);
            fma2(acc[5][2], b23.x, ap); fma2(acc[5][3], b23.y, ap);
            ap = pack2(a1.z);
            fma2(acc[6][0], b01.x, ap); fma2(acc[6][1], b01.y, ap);
            fma2(acc[6][2], b23.x, ap); fma2(acc[6][3], b23.y, ap);
            ap = pack2(a1.w);
            fma2(acc[7][0], b01.x, ap); fma2(acc[7][1], b01.y, ap);
            fma2(acc[7][2], b23.x, ap); fma2(acc[7][3], b23.y, ap);
        }

        if (kt < 31) {
#pragma unroll
            for (int it = 0; it < 8; ++it) {
                int idx = it * 256 + tid;
                int kk = idx >> 7, row = idx & 127;
                Asn[kk * 132 + row] = a_pre[it];
            }
#pragma unroll
            for (int it = 0; it < 2; ++it) {
                int idx = it * 256 + tid;
                int kk = idx >> 5, c4 = idx & 31;
                *reinterpret_cast<float4*>(&Bsn[kk * 132 + c4 * 4]) = b_pre[it];
            }
        }
        __syncthreads();
    }

#pragma unroll
    for (int rr = 0; rr < 8; ++rr) {
        size_t row = (size_t)r0 + ty * 8 + rr;
        float* qp = g_Q + row * 512 + n0 + tx * 8;
        float2 f0 = unpack2(acc[rr][0]);
        float2 f1 = unpack2(acc[rr][1]);
        float2 f2 = unpack2(acc[rr][2]);
        float2 f3 = unpack2(acc[rr][3]);
        float4 v0; v0.x = f0.x; v0.y = f0.y; v0.z = f1.x; v0.w = f1.y;
        float4 v1; v1.x = f2.x; v1.y = f2.y; v1.z = f3.x; v1.w = f3.y;
        *reinterpret_cast<float4*>(qp)     = v0;
        *reinterpret_cast<float4*>(qp + 4) = v1;
    }
}

// ---------------- K4b: A = Q D2 Q^T + W1_lo D1 W1_lo^T ; rhs -= Q w (round-4 exact) ----------------
#define K4B_FLOATS (512*17 + 128*68 + 8*512 + 8*64 + 8*64)
#define K4B_SMEM   (K4B_FLOATS * 4)

__global__ __launch_bounds__(256, 2) void k4b_assemble(const float* __restrict__ W1) {
    extern __shared__ float smb[];
    float* W1s = smb;                 // [k*17 + i]
    float* Qc  = W1s + 512 * 17;      // [(s*16+i)*68 + m]
    float* d1s = Qc + 128 * 68;       // [s*512 + k]
    float* d2c = d1s + 8 * 512;       // [s*64 + m]
    float* wc  = d2c + 8 * 64;        // [s*64 + m]

    int tid = threadIdx.x;
    int b0  = blockIdx.x * 8;

    for (int idx = tid; idx < 16 * 512; idx += 256) {
        int i = idx >> 9, k = idx & 511;
        W1s[k * 17 + i] = W1[(16 + i) * 512 + k];
    }
    for (int idx = tid; idx < 8 * 512; idx += 256)
        d1s[idx] = g_g1[(size_t)b0 * 512 + idx];

    int s = tid >> 5, lane = tid & 31;
    int rg = lane >> 3, cg = lane & 7;

    float A0[4] = {}, A1[4] = {}, rhs2[4] = {};

    for (int mc = 0; mc < 8; ++mc) {
        int m0 = mc * 64;
        __syncthreads();
#pragma unroll
        for (int it = 0; it < 8; ++it) {
            int idx = it * 256 + tid;
            int ss = idx >> 8, rem = idx & 255;
            int i = rem >> 4, c4 = rem & 15;
            *reinterpret_cast<float4*>(&Qc[(ss * 16 + i) * 68 + c4 * 4]) =
                *reinterpret_cast<const float4*>(&g_Q[((size_t)(b0 + ss) * 16 + i) * 512 + m0 + c4 * 4]);
        }
        for (int idx = tid; idx < 512; idx += 256) {
            int ss = idx >> 6, m = idx & 63;
            d2c[idx] = g_d2[(size_t)(b0 + ss) * 512 + m0 + m];
            wc[idx]  = g_w [(size_t)(b0 + ss) * 512 + m0 + m];
        }
        __syncthreads();

        const float* qb = Qc + s * 16 * 68;
        const float* dp = d2c + s * 64;
        const float* wp = wc + s * 64;
#pragma unroll 4
        for (int m = 0; m < 64; ++m) {
            float d2v = dp[m], wv = wp[m];
            float qj0 = qb[(2 * cg) * 68 + m];
            float qj1 = qb[(2 * cg + 1) * 68 + m];
#pragma unroll
            for (int rr = 0; rr < 4; ++rr) {
                float qi = qb[(4 * rg + rr) * 68 + m];
                float t = qi * d2v;
                A0[rr] = fmaf(t, qj0, A0[rr]);
                A1[rr] = fmaf(t, qj1, A1[rr]);
                rhs2[rr] = fmaf(qi, wv, rhs2[rr]);
            }
        }
    }

    // H1 term
    {
        const float* d1p = d1s + s * 512;
#pragma unroll 2
        for (int k = 0; k < 512; ++k) {
            float d1v = d1p[k];
            const float* wk = W1s + k * 17;
            float wj0 = wk[2 * cg], wj1 = wk[2 * cg + 1];
#pragma unroll
            for (int rr = 0; rr < 4; ++rr) {
                float t = wk[4 * rg + rr] * d1v;
                A0[rr] = fmaf(t, wj0, A0[rr]);
                A1[rr] = fmaf(t, wj1, A1[rr]);
            }
        }
    }

    int b = b0 + s;
#pragma unroll
    for (int rr = 0; rr < 4; ++rr) {
        int i = 4 * rg + rr;
        float* Ar = g_A + ((size_t)b * 16 + i) * 16;
        Ar[2 * cg]     = A0[rr];
        Ar[2 * cg + 1] = A1[rr];
        if (cg == 0) {
            size_t ob = (size_t)b * 16 + i;
            g_rhs[ob] -= rhs2[rr];
        }
    }
}

// ---------------- K5: per-sample symmetric Jacobi eigensolver + pinv (round-4 exact) ----------------
#define PINV_RCOND 1.9073486e-5f
#define JACOBI_SWEEPS 8

__global__ __launch_bounds__(256) void k5_pinv(const float* __restrict__ x,
                                               float* __restrict__ out) {
    __shared__ float sm[16 * 592];
    int tid = threadIdx.x;
    int sI = tid >> 4;
    int r  = tid & 15;
    int b  = blockIdx.x * 16 + sI;

    float* As = sm + sI * 592;
    float* Vs = As + 272;
    float* ys = Vs + 272;
    float* rs = ys + 16;

    {
        const float* Ag = g_A + ((size_t)b * 16 + r) * 16;
#pragma unroll
        for (int j = 0; j < 16; ++j) {
            As[r * 17 + j] = Ag[j];
            Vs[r * 17 + j] = (r == j) ? 1.f : 0.f;
        }
        rs[r] = g_rhs[(size_t)b * 16 + r];
    }
    __syncwarp();

    for (int sweep = 0; sweep < JACOBI_SWEEPS; ++sweep) {
        for (int p = 0; p < 15; ++p) {
            for (int q = p + 1; q < 16; ++q) {
                float apq = As[p * 17 + q];
                float app = As[p * 17 + p];
                float aqq = As[q * 17 + q];
                float aip = As[r * 17 + p];
                float aiq = As[r * 17 + q];
                float vip = Vs[r * 17 + p];
                float viq = Vs[r * 17 + q];
                __syncwarp();
                float tau = (aqq - app) / (2.f * apq);
                float tt  = copysignf(1.f, tau) / (fabsf(tau) + sqrtf(fmaf(tau, tau, 1.f)));
                float t   = (fabsf(apq) > 0.f) ? tt : 0.f;
                float c   = 1.f / sqrtf(fmaf(t, t, 1.f));
                float s   = t * c;
                float nip = c * aip - s * aiq;
                float niq = s * aip + c * aiq;
                if (r != p && r != q) {
                    As[r * 17 + p] = nip; As[p * 17 + r] = nip;
                    As[r * 17 + q] = niq; As[q * 17 + r] = niq;
                }
                if (r == p) {
                    As[p * 17 + p] = app - t * apq;
                    As[q * 17 + q] = aqq + t * apq;
                    As[p * 17 + q] = 0.f;
                    As[q * 17 + p] = 0.f;
                }
                Vs[r * 17 + p] = c * vip - s * viq;
                Vs[r * 17 + q] = s * vip + c * viq;
                __syncwarp();
            }
        }
    }

    float lam = As[r * 17 + r];
    float m = fabsf(lam);
#pragma unroll
    for (int off = 8; off > 0; off >>= 1)
        m = fmaxf(m, __shfl_xor_sync(0xffffffffu, m, off));
    float cutoff = PINV_RCOND * m;

    float acc = 0.f;
#pragma unroll
    for (int j = 0; j < 16; ++j) acc = fmaf(Vs[j * 17 + r], rs[j], acc);
    ys[r] = (fabsf(lam) > cutoff) ? (acc / lam) : 0.f;
    __syncwarp();

    float qdd = 0.f;
#pragma unroll
    for (int j = 0; j < 16; ++j) qdd = fmaf(Vs[r * 17 + j], ys[j], qdd);

    out[(size_t)b * 32 + 16 + r] = qdd;
    out[(size_t)b * 32 + r]      = x[(size_t)b * 32 + 16 + r];
}

// ---------------- launch ----------------
extern "C" void kernel_launch(void* const* d_in, const int* in_sizes, int n_in,
                              void* d_out, int out_size) {
    const float* x  = (const float*)d_in[0];
    const float* W1 = (const float*)d_in[1];
    const float* b1 = (const float*)d_in[2];
    const float* W2 = (const float*)d_in[3];
    const float* b2 = (const float*)d_in[4];
    const float* W3 = (const float*)d_in[5];
    float* out = (float*)d_out;
    (void)in_sizes; (void)n_in; (void)out_size;

    cudaFuncSetAttribute(k1_layer1,    cudaFuncAttributeMaxDynamicSharedMemorySize, K1_SMEM);
    cudaFuncSetAttribute(k_jac,        cudaFuncAttributeMaxDynamicSharedMemorySize, KJ_SMEM);
    cudaFuncSetAttribute(k4a_qgemm,    cudaFuncAttributeMaxDynamicSharedMemorySize, K4A_SMEM);
    cudaFuncSetAttribute(k4b_assemble, cudaFuncAttributeMaxDynamicSharedMemorySize, K4B_SMEM);

    k1_layer1<<<BS / 8, 256, K1_SMEM>>>(x, W1, b1);
    k2_layer2<<<dim3(BS / 64, HID / 64), 256>>>(W2, b2, W3);
    k3_g1<<<dim3(BS / 64, HID / 64), 256>>>(W2);
    k_jac<<<BS / 8, 256, KJ_SMEM>>>(W1);
    k4a_qgemm<<<dim3(BS * 16 / 128, HID / 128), 256, K4A_SMEM>>>(W1, W2);
    k4b_assemble<<<BS / 8, 256, K4B_SMEM>>>(W1);
    k5_pinv<<<BS / 16, 256>>>(x, out);
}